// round 15
// baseline (speedup 1.0000x reference)
#include <cuda_runtime.h>
#include <cuda_fp16.h>
#include <math.h>
#include <stdint.h>

#define SEQ     2048
#define DMODEL  512
#define NH      8
#define DH      64
#define BATCH   2
#define MTOT    4096

// ---------------- scratch (__device__ globals, allocation-free) -------------
__device__ __half g_xh[MTOT * DMODEL];
__device__ __half g_xl[MTOT * DMODEL];
__device__ __half g_wh[3 * DMODEL * DMODEL];   // [Wq;Wk;Wv] rows 0..1535 (hi)
__device__ __half g_wl[3 * DMODEL * DMODEL];   // lo used only for Wv range
__device__ __half g_oh[DMODEL * DMODEL];
__device__ __half g_ol[DMODEL * DMODEL];
__device__ float  g_V [MTOT * DMODEL];
__device__ __half g_zh[MTOT * DMODEL];
__device__ __half g_zl[MTOT * DMODEL];
__device__ float  g_sa[16 * SEQ];
__device__ float  g_sc[16 * SEQ];
__device__ float  g_cs[16 * 128 * 64];   // [bh][chunk16][dh] fine V sums
__device__ float  g_cb[16 * 16 * 64];    // [bh][mblk128][dh] coarse V sums

// ---------------------------------------------------------------------------
__device__ __forceinline__ uint32_t smem_u32(const void* p) {
    uint32_t a;
    asm("{ .reg .u64 t; cvta.to.shared.u64 t, %1; cvt.u32.u64 %0, t; }"
        : "=r"(a) : "l"(p));
    return a;
}

#define CPASYNC(d, s) \
    asm volatile("cp.async.cg.shared.global [%0], [%1], 16;" \
                 :: "r"(d), "l"(s) : "memory")

#define LDSM4(r, a) \
    asm volatile("ldmatrix.sync.aligned.m8n8.x4.shared.b16 {%0,%1,%2,%3}, [%4];" \
                 : "=r"((r)[0]), "=r"((r)[1]), "=r"((r)[2]), "=r"((r)[3]) \
                 : "r"(a))

#define MMA(d, a, b0, b1) \
    asm volatile("mma.sync.aligned.m16n8k16.row.col.f32.f16.f16.f32 " \
                 "{%0,%1,%2,%3},{%4,%5,%6,%7},{%8,%9},{%0,%1,%2,%3};" \
                 : "+f"((d)[0]), "+f"((d)[1]), "+f"((d)[2]), "+f"((d)[3]) \
                 : "r"((a)[0]), "r"((a)[1]), "r"((a)[2]), "r"((a)[3]), \
                   "r"(b0), "r"(b1))

// 128x64 BK=32 tiling, 3-stage pipeline
#define SROW2 40                         // 32 halves + 8 pad
#define A_MAT (128 * SROW2)              // halves
#define B_MAT (64 * SROW2)
#define STAGEH (2 * A_MAT + 2 * B_MAT)   // V/out stage (Ah,Al,Bh,Bl) halves
#define SMEM64 (3 * STAGEH * 2)          // 92160 B
#define STAGEQK (A_MAT + 2 * B_MAT)      // QK stage (A,BQ,BK) halves

// Fragment load for fp16x3 branch: all frags of one kk
#define LDFRAG3(base, kkv, A0, A1, A2, A3, B0h, B0l, B1h, B1l) { \
    const uint32_t aH = (base) + a_row_off + (kkv) * 32; \
    const uint32_t aL = aH + A_MAT * 2; \
    LDSM4(A0, aH); \
    LDSM4(A1, aH + 16 * SROW2 * 2); \
    LDSM4(A2, aL); \
    LDSM4(A3, aL + 16 * SROW2 * 2); \
    const uint32_t bH = (base) + 2 * A_MAT * 2 + b_row_off + (kkv) * 32; \
    const uint32_t bL = bH + B_MAT * 2; \
    LDSM4(B0h, bH); \
    LDSM4(B0l, bL); \
    LDSM4(B1h, bH + 16 * SROW2 * 2); \
    LDSM4(B1l, bL + 16 * SROW2 * 2); \
}

// 24 MMAs of one kk for fp16x3 branch
#define MMAS3(A0, A1, A2, A3, B0h, B0l, B1h, B1l) { \
    MMA(acc[0][0], A0, B0h[0], B0h[1]); \
    MMA(acc[1][0], A1, B0h[0], B0h[1]); \
    MMA(acc[0][1], A0, B0h[2], B0h[3]); \
    MMA(acc[1][1], A1, B0h[2], B0h[3]); \
    MMA(acc[0][2], A0, B1h[0], B1h[1]); \
    MMA(acc[1][2], A1, B1h[0], B1h[1]); \
    MMA(acc[0][3], A0, B1h[2], B1h[3]); \
    MMA(acc[1][3], A1, B1h[2], B1h[3]); \
    MMA(acc[0][0], A2, B0h[0], B0h[1]); \
    MMA(acc[1][0], A3, B0h[0], B0h[1]); \
    MMA(acc[0][1], A2, B0h[2], B0h[3]); \
    MMA(acc[1][1], A3, B0h[2], B0h[3]); \
    MMA(acc[0][2], A2, B1h[0], B1h[1]); \
    MMA(acc[1][2], A3, B1h[0], B1h[1]); \
    MMA(acc[0][3], A2, B1h[2], B1h[3]); \
    MMA(acc[1][3], A3, B1h[2], B1h[3]); \
    MMA(acc[0][0], A0, B0l[0], B0l[1]); \
    MMA(acc[1][0], A1, B0l[0], B0l[1]); \
    MMA(acc[0][1], A0, B0l[2], B0l[3]); \
    MMA(acc[1][1], A1, B0l[2], B0l[3]); \
    MMA(acc[0][2], A0, B1l[0], B1l[1]); \
    MMA(acc[1][2], A1, B1l[0], B1l[1]); \
    MMA(acc[0][3], A0, B1l[2], B1l[3]); \
    MMA(acc[1][3], A1, B1l[2], B1l[3]); \
}

// ---------------------------------------------------------------------------
// fp32 -> fp16 hi/lo conversion (lo skipped for Wq/Wk)
// ---------------------------------------------------------------------------
__global__ __launch_bounds__(256) void convert_all(
    const float* __restrict__ x,  const float* __restrict__ wq,
    const float* __restrict__ wk, const float* __restrict__ wv,
    const float* __restrict__ wo)
{
    int t = blockIdx.x * 256 + threadIdx.x;       // float4 index, 786432 total
    const float* src;
    __half *dh, *dl;
    int idx;
    bool wantLo = true;
    if (t < 524288)      { src = x;  dh = g_xh;          dl = g_xl;          idx = t; }
    else if (t < 589824) { src = wq; dh = g_wh;          dl = g_wl;          idx = t - 524288; wantLo = false; }
    else if (t < 655360) { src = wk; dh = g_wh + 262144; dl = g_wl + 262144; idx = t - 589824; wantLo = false; }
    else if (t < 720896) { src = wv; dh = g_wh + 524288; dl = g_wl + 524288; idx = t - 655360; }
    else                 { src = wo; dh = g_oh;          dl = g_ol;          idx = t - 720896; }

    float4 v = ((const float4*)src)[idx];
    __half h0 = __float2half_rn(v.x), h1 = __float2half_rn(v.y);
    __half h2 = __float2half_rn(v.z), h3 = __float2half_rn(v.w);
    __half2* ph = (__half2*)(dh + idx * 4);
    ph[0] = __halves2half2(h0, h1); ph[1] = __halves2half2(h2, h3);
    if (wantLo) {
        __half l0 = __float2half_rn(v.x - __half2float(h0));
        __half l1 = __float2half_rn(v.y - __half2float(h1));
        __half l2 = __float2half_rn(v.z - __half2float(h2));
        __half l3 = __float2half_rn(v.w - __half2float(h3));
        __half2* pl = (__half2*)(dl + idx * 4);
        pl[0] = __halves2half2(l0, l1); pl[1] = __halves2half2(l2, l3);
    }
}

// ---------------------------------------------------------------------------
// Fused QK-diag + V-projection. grid (16, 32), both 128x64/BK=32, 3-stage,
// one barrier per chunk, fragment-batched loads, 2 CTAs/SM.
// ---------------------------------------------------------------------------
__global__ __launch_bounds__(256, 2) void qkv_fused(
    const __half* __restrict__ xh, const __half* __restrict__ xl,
    const __half* __restrict__ wh, const __half* __restrict__ wl,
    float* __restrict__ V)
{
    extern __shared__ __half sm[];
    const uint32_t sb = smem_u32(sm);
    const int tid = threadIdx.x;
    const int lane = tid & 31, wid = tid >> 5;
    const int wm = wid & 3, wn = wid >> 2;
    const int m0 = blockIdx.y * 128;

    const int lrA = tid >> 1, lpA = tid & 1;
    const int lrB = tid >> 2, lpB = tid & 3;
    const uint32_t dA = sb + (uint32_t)(lrA * SROW2 + lpA * 16) * 2;
    const uint32_t dB = sb + (uint32_t)(lrB * SROW2 + lpB * 8) * 2;

    const uint32_t a_row_off =
        (uint32_t)((wm * 32 + (lane & 15)) * SROW2) * 2 + (uint32_t)((lane >> 4) * 16);
    const int bn = wn * 32 + (lane & 7) + ((lane >> 4) << 3);
    const uint32_t b_row_off =
        (uint32_t)(bn * SROW2) * 2 + (uint32_t)(((lane >> 3) & 1) * 16);

    if (blockIdx.x < 8) {
        // ================= QK-diagonal branch (plain fp16) ==================
        const int n0 = blockIdx.x * 64;   // head = blockIdx.x
        const __half* gA = xh + (size_t)(m0 + lrA) * 512 + lpA * 16;
        const __half* gQ = wh + (size_t)(n0 + lrB) * 512 + lpB * 8;
        const __half* gK = wh + 512 * 512 + (size_t)(n0 + lrB) * 512 + lpB * 8;

#define LOADQK(c, s) { \
        const uint32_t soff = (uint32_t)(s) * (STAGEQK * 2); \
        const int ko = (c) * 32; \
        CPASYNC(dA + soff + 0,  gA + ko); \
        CPASYNC(dA + soff + 16, gA + ko + 8); \
        CPASYNC(dB + soff + A_MAT * 2, gQ + ko); \
        CPASYNC(dB + soff + A_MAT * 2 + B_MAT * 2, gK + ko); \
    }

#define LDFRAGQK(base, kkv, A0, A1, B0q, B0k, B1q, B1k) { \
        const uint32_t aA = (base) + a_row_off + (kkv) * 32; \
        LDSM4(A0, aA); \
        LDSM4(A1, aA + 16 * SROW2 * 2); \
        const uint32_t bQ = (base) + A_MAT * 2 + b_row_off + (kkv) * 32; \
        const uint32_t bK = bQ + B_MAT * 2; \
        LDSM4(B0q, bQ); \
        LDSM4(B0k, bK); \
        LDSM4(B1q, bQ + 16 * SROW2 * 2); \
        LDSM4(B1k, bK + 16 * SROW2 * 2); \
    }

#define MMASQK(A0, A1, B0q, B0k, B1q, B1k) { \
        MMA(aq[0][0], A0, B0q[0], B0q[1]); \
        MMA(aq[1][0], A1, B0q[0], B0q[1]); \
        MMA(aq[0][1], A0, B0q[2], B0q[3]); \
        MMA(aq[1][1], A1, B0q[2], B0q[3]); \
        MMA(aq[0][2], A0, B1q[0], B1q[1]); \
        MMA(aq[1][2], A1, B1q[0], B1q[1]); \
        MMA(aq[0][3], A0, B1q[2], B1q[3]); \
        MMA(aq[1][3], A1, B1q[2], B1q[3]); \
        MMA(ak[0][0], A0, B0k[0], B0k[1]); \
        MMA(ak[1][0], A1, B0k[0], B0k[1]); \
        MMA(ak[0][1], A0, B0k[2], B0k[3]); \
        MMA(ak[1][1], A1, B0k[2], B0k[3]); \
        MMA(ak[0][2], A0, B1k[0], B1k[1]); \
        MMA(ak[1][2], A1, B1k[0], B1k[1]); \
        MMA(ak[0][3], A0, B1k[2], B1k[3]); \
        MMA(ak[1][3], A1, B1k[2], B1k[3]); \
    }

        float aq[2][4][4], ak[2][4][4];
#pragma unroll
        for (int i = 0; i < 2; i++)
#pragma unroll
            for (int j = 0; j < 4; j++)
#pragma unroll
                for (int k = 0; k < 4; k++) { aq[i][j][k] = 0.0f; ak[i][j][k] = 0.0f; }

        LOADQK(0, 0);
        asm volatile("cp.async.commit_group;" ::: "memory");
        LOADQK(1, 1);
        asm volatile("cp.async.commit_group;" ::: "memory");

        for (int c = 0; c < 16; c++) {
            if (c < 15) {
                asm volatile("cp.async.wait_group 1;" ::: "memory");
            } else {
                asm volatile("cp.async.wait_group 0;" ::: "memory");
            }
            __syncthreads();

            const uint32_t base = sb + (uint32_t)(c % 3) * (STAGEQK * 2);
            uint32_t x00[4], x01[4], y00[4], y01[4], y02[4], y03[4];
            uint32_t x10[4], x11[4], y10[4], y11[4], y12[4], y13[4];
            LDFRAGQK(base, 0, x00, x01, y00, y01, y02, y03);
            LDFRAGQK(base, 1, x10, x11, y10, y11, y12, y13);

            if (c < 14) {
                LOADQK(c + 2, (c + 2) % 3);
                asm volatile("cp.async.commit_group;" ::: "memory");
            }

            MMASQK(x00, x01, y00, y01, y02, y03);
            MMASQK(x10, x11, y10, y11, y12, y13);
        }
        __syncthreads();

        float pj[4];
#pragma unroll
        for (int j = 0; j < 4; j++) {
            const int mi = j >> 1, o = (j & 1) * 2;
            float p = 0.0f;
#pragma unroll
            for (int ni = 0; ni < 4; ni++)
                p += aq[mi][ni][o] * ak[mi][ni][o]
                   + aq[mi][ni][o + 1] * ak[mi][ni][o + 1];
            p += __shfl_xor_sync(0xFFFFFFFF, p, 1);
            p += __shfl_xor_sync(0xFFFFFFFF, p, 2);
            pj[j] = p;
        }

        float* buf = (float*)sm;   // 128 floats
        if (wn == 1 && (lane & 3) == 0) {
#pragma unroll
            for (int j = 0; j < 4; j++)
                buf[(wm * 4 + j) * 8 + (lane >> 2)] = pj[j];
        }
        __syncthreads();
        if (wn == 0 && (lane & 3) == 0) {
            const int h = blockIdx.x;
#pragma unroll
            for (int j = 0; j < 4; j++) {
                float p = pj[j] + buf[(wm * 4 + j) * 8 + (lane >> 2)];
                const int m = m0 + wm * 32 + (lane >> 2) + (j >> 1) * 16 + (j & 1) * 8;
                const int b = m >> 11, q = m & 2047;
                float sd = p * 0.125f;
                int cnt = SEQ - 1 - q;
                float mx = (cnt > 0) ? fmaxf(sd, 0.0f) : sd;
                float ed = expf(sd - mx);
                float eo = (cnt > 0) ? expf(-mx) : 0.0f;
                float Z = ed + (float)cnt * eo;
                g_sa[(b * 8 + h) * SEQ + q] = ed / Z;
                g_sc[(b * 8 + h) * SEQ + q] = eo / Z;
            }
        }
    } else {
        // ================= V branch (fp16x3) ================================
        const int n0 = (blockIdx.x - 8) * 64;
        const __half* gAh = xh + (size_t)(m0 + lrA) * 512 + lpA * 16;
        const __half* gAl = xl + (size_t)(m0 + lrA) * 512 + lpA * 16;
        const __half* gBh = wh + 1024 * 512 + (size_t)(n0 + lrB) * 512 + lpB * 8;
        const __half* gBl = wl + 1024 * 512 + (size_t)(n0 + lrB) * 512 + lpB * 8;

#define LOADCH64(c, s) { \
        const uint32_t soff = (uint32_t)(s) * (STAGEH * 2); \
        const int ko = (c) * 32; \
        CPASYNC(dA + soff + 0 * A_MAT * 2 + 0,  gAh + ko); \
        CPASYNC(dA + soff + 0 * A_MAT * 2 + 16, gAh + ko + 8); \
        CPASYNC(dA + soff + 1 * A_MAT * 2 + 0,  gAl + ko); \
        CPASYNC(dA + soff + 1 * A_MAT * 2 + 16, gAl + ko + 8); \
        CPASYNC(dB + soff + 2 * A_MAT * 2 + 0,  gBh + ko); \
        CPASYNC(dB + soff + 2 * A_MAT * 2 + B_MAT * 2, gBl + ko); \
    }

        float acc[2][4][4];
#pragma unroll
        for (int i = 0; i < 2; i++)
#pragma unroll
            for (int j = 0; j < 4; j++)
#pragma unroll
                for (int k = 0; k < 4; k++) acc[i][j][k] = 0.0f;

        LOADCH64(0, 0);
        asm volatile("cp.async.commit_group;" ::: "memory");
        LOADCH64(1, 1);
        asm volatile("cp.async.commit_group;" ::: "memory");

        for (int c = 0; c < 16; c++) {
            if (c < 15) {
                asm volatile("cp.async.wait_group 1;" ::: "memory");
            } else {
                asm volatile("cp.async.wait_group 0;" ::: "memory");
            }
            __syncthreads();

            const uint32_t base = sb + (uint32_t)(c % 3) * (STAGEH * 2);
            uint32_t p00[4], p01[4], p02[4], p03[4], q00[4], q01[4], q02[4], q03[4];
            uint32_t p10[4], p11[4], p12[4], p13[4], q10[4], q11[4], q12[4], q13[4];
            LDFRAG3(base, 0, p00, p01, p02, p03, q00, q01, q02, q03);
            LDFRAG3(base, 1, p10, p11, p12, p13, q10, q11, q12, q13);

            if (c < 14) {
                LOADCH64(c + 2, (c + 2) % 3);
                asm volatile("cp.async.commit_group;" ::: "memory");
            }

            MMAS3(p00, p01, p02, p03, q00, q01, q02, q03);
            MMAS3(p10, p11, p12, p13, q10, q11, q12, q13);
        }
        __syncthreads();

        // Epilogue: fp32 V store
        const int r0 = m0 + wm * 32 + (lane >> 2);
        const int cb2 = n0 + wn * 32 + (lane & 3) * 2;
#pragma unroll
        for (int mi = 0; mi < 2; mi++) {
            const int r = r0 + mi * 16;
#pragma unroll
            for (int ni = 0; ni < 4; ni++) {
                const int cg = cb2 + ni * 8;
                *(float2*)&V[(size_t)r * 512 + cg] =
                    make_float2(acc[mi][ni][0], acc[mi][ni][1]);
                *(float2*)&V[(size_t)(r + 8) * 512 + cg] =
                    make_float2(acc[mi][ni][2], acc[mi][ni][3]);
            }
        }

        // Fine 16-row chunk sums + coarse 128-row sums
        const int b = m0 >> 11;
        const int c16 = ((m0 & 2047) >> 4) + wm * 2;
        const int h = n0 >> 6;
        const int bh = b * 8 + h;
        float* cbuf = (float*)sm;   // [4 wm][64 dh]
#pragma unroll
        for (int ni = 0; ni < 4; ni++) {
            float t0 = 0.0f, t1 = 0.0f;
#pragma unroll
            for (int mi = 0; mi < 2; mi++) {
                float s0 = acc[mi][ni][0] + acc[mi][ni][2];
                float s1 = acc[mi][ni][1] + acc[mi][ni][3];
#pragma unroll
                for (int st = 4; st < 32; st <<= 1) {
                    s0 += __shfl_xor_sync(0xFFFFFFFF, s0, st);
                    s1 += __shfl_xor_sync(0xFFFFFFFF, s1, st);
                }
                if (lane < 4) {
                    const int dh = wn * 32 + (lane << 1) + ni * 8;
                    *(float2*)&g_cs[((size_t)bh * 128 + c16 + mi) * 64 + dh] =
                        make_float2(s0, s1);
                }
                t0 += s0; t1 += s1;
            }
            if (lane < 4) {
                const int dh = wn * 32 + (lane << 1) + ni * 8;
                cbuf[wm * 64 + dh]     = t0;
                cbuf[wm * 64 + dh + 1] = t1;
            }
        }
        __syncthreads();
        if (tid < 64) {
            const int mblk = (m0 & 2047) >> 7;   // 0..15
            g_cb[((size_t)bh * 16 + mblk) * 64 + tid] =
                cbuf[tid] + cbuf[64 + tid] + cbuf[128 + tid] + cbuf[192 + tid];
        }
    }
}

// ---------------------------------------------------------------------------
// fp16x3 GEMM, 128x64/BK=32, 3-stage, fragment-batched — out projection.
// ---------------------------------------------------------------------------
__global__ __launch_bounds__(256, 2) void gemm64(
    const __half* __restrict__ Ah, const __half* __restrict__ Al,
    const __half* __restrict__ Bh, const __half* __restrict__ Bl,
    float* __restrict__ C)
{
    extern __shared__ __half sm[];
    const uint32_t sb = smem_u32(sm);
    const int tid = threadIdx.x;
    const int lane = tid & 31, wid = tid >> 5;
    const int wm = wid & 3, wn = wid >> 2;
    const int n0 = blockIdx.x * 64, m0 = blockIdx.y * 128;

    const int lrA = tid >> 1, lpA = tid & 1;
    const int lrB = tid >> 2, lpB = tid & 3;
    const __half* gAh = Ah + (size_t)(m0 + lrA) * 512 + lpA * 16;
    const __half* gAl = Al + (size_t)(m0 + lrA) * 512 + lpA * 16;
    const __half* gBh = Bh + (size_t)(n0 + lrB) * 512 + lpB * 8;
    const __half* gBl = Bl + (size_t)(n0 + lrB) * 512 + lpB * 8;
    const uint32_t dA = sb + (uint32_t)(lrA * SROW2 + lpA * 16) * 2;
    const uint32_t dB = sb + (uint32_t)(lrB * SROW2 + lpB * 8) * 2;

#define LOADCHO(c, s) { \
        const uint32_t soff = (uint32_t)(s) * (STAGEH * 2); \
        const int ko = (c) * 32; \
        CPASYNC(dA + soff + 0 * A_MAT * 2 + 0,  gAh + ko); \
        CPASYNC(dA + soff + 0 * A_MAT * 2 + 16, gAh + ko + 8); \
        CPASYNC(dA + soff + 1 * A_MAT * 2 + 0,  gAl + ko); \
        CPASYNC(dA + soff + 1 * A_MAT * 2 + 16, gAl + ko + 8); \
        CPASYNC(dB + soff + 2 * A_MAT * 2 + 0,  gBh + ko); \
        CPASYNC(dB + soff + 2 * A_MAT * 2 + B_MAT * 2, gBl + ko); \
    }

    float acc[2][4][4];
#pragma unroll
    for (int i = 0; i < 2; i++)
#pragma unroll
        for (int j = 0; j < 4; j++)
#pragma unroll
            for (int k = 0; k < 4; k++) acc[i][j][k] = 0.0f;

    LOADCHO(0, 0);
    asm volatile("cp.async.commit_group;" ::: "memory");
    LOADCHO(1, 1);
    asm volatile("cp.async.commit_group;" ::: "memory");

    const uint32_t a_row_off =
        (uint32_t)((wm * 32 + (lane & 15)) * SROW2) * 2 + (uint32_t)((lane >> 4) * 16);
    const int bn = wn * 32 + (lane & 7) + ((lane >> 4) << 3);
    const uint32_t b_row_off =
        (uint32_t)(bn * SROW2) * 2 + (uint32_t)(((lane >> 3) & 1) * 16);

    for (int c = 0; c < 16; c++) {
        if (c < 15) {
            asm volatile("cp.async.wait_group 1;" ::: "memory");
        } else {
            asm volatile("cp.async.wait_group 0;" ::: "memory");
        }
        __syncthreads();

        const uint32_t base = sb + (uint32_t)(c % 3) * (STAGEH * 2);
        uint32_t p00[4], p01[4], p02[4], p03[4], q00[4], q01[4], q02[4], q03[4];
        uint32_t p10[4], p11[4], p12[4], p13[4], q10[4], q11[4], q12[4], q13[4];
        LDFRAG3(base, 0, p00, p01, p02, p03, q00, q01, q02, q03);
        LDFRAG3(base, 1, p10, p11, p12, p13, q10, q11, q12, q13);

        if (c < 14) {
            LOADCHO(c + 2, (c + 2) % 3);
            asm volatile("cp.async.commit_group;" ::: "memory");
        }

        MMAS3(p00, p01, p02, p03, q00, q01, q02, q03);
        MMAS3(p10, p11, p12, p13, q10, q11, q12, q13);
    }

    const int r0 = m0 + wm * 32 + (lane >> 2);
    const int cb = n0 + wn * 32 + (lane & 3) * 2;
#pragma unroll
    for (int mi = 0; mi < 2; mi++) {
        const int r = r0 + mi * 16;
#pragma unroll
        for (int ni = 0; ni < 4; ni++) {
            const int cg = cb + ni * 8;
            *(float2*)&C[(size_t)r * 512 + cg] =
                make_float2(acc[mi][ni][0], acc[mi][ni][1]);
            *(float2*)&C[(size_t)(r + 8) * 512 + cg] =
                make_float2(acc[mi][ni][2], acc[mi][ni][3]);
        }
    }
}

// ---------------------------------------------------------------------------
// Scan: z[q] = a_q*v[q] + c_q*suffix_{p>q} v[p]. Run-in from coarse + fine sums.
// ---------------------------------------------------------------------------
__global__ __launch_bounds__(256) void v_scan()
{
    int bh = blockIdx.y;
    int chunk = blockIdx.x * 4 + (threadIdx.x >> 6);   // 0..127
    int dh = threadIdx.x & 63;
    int b = bh >> 3, h = bh & 7;
    const int q0 = chunk * 16;

    // Run-in: coarse 128-row blocks after this chunk's block + fine chunks
    const int cbk = chunk >> 3;
    float run = 0.0f;
    const float* cbp = g_cb + ((size_t)bh * 16) * 64 + dh;
    for (int j = cbk + 1; j < 16; j++) run += cbp[(size_t)j * 64];
    const float* csp = g_cs + ((size_t)bh * 128) * 64 + dh;
    const int cfEnd = (cbk + 1) << 3;
    for (int cf = chunk + 1; cf < cfEnd; cf++) run += csp[(size_t)cf * 64];

    // Batch all loads up front
    const float* vbase = g_V + (size_t)(b * SEQ + q0) * DMODEL + h * DH + dh;
    float v[16];
#pragma unroll
    for (int i = 0; i < 16; i++) v[i] = vbase[i * DMODEL];

    float wa[16], wc[16];
    const float* sa = g_sa + bh * SEQ + q0;
    const float* sc = g_sc + bh * SEQ + q0;
#pragma unroll
    for (int i = 0; i < 16; i++) { wa[i] = sa[i]; wc[i] = sc[i]; }

    __half* zhb = g_zh + (size_t)(b * SEQ + q0) * DMODEL + h * DH + dh;
    __half* zlb = g_zl + (size_t)(b * SEQ + q0) * DMODEL + h * DH + dh;
#pragma unroll
    for (int i = 15; i >= 0; i--) {
        float z = wa[i] * v[i] + wc[i] * run;
        __half zh = __float2half_rn(z);
        zhb[i * DMODEL] = zh;
        zlb[i * DMODEL] = __float2half_rn(z - __half2float(zh));
        run += v[i];
    }
}

// ---------------------------------------------------------------------------
extern "C" void kernel_launch(void* const* d_in, const int* in_sizes, int n_in,
                              void* d_out, int out_size)
{
    const float* x  = (const float*)d_in[0];
    const float* WQ = (const float*)d_in[1];
    const float* WK = (const float*)d_in[2];
    const float* WV = (const float*)d_in[3];
    const float* WO = (const float*)d_in[4];
    float* out = (float*)d_out;

    cudaFuncSetAttribute(qkv_fused, cudaFuncAttributeMaxDynamicSharedMemorySize,
                         SMEM64);
    cudaFuncSetAttribute(gemm64, cudaFuncAttributeMaxDynamicSharedMemorySize,
                         SMEM64);

    __half *xh, *xl, *wh, *wl, *oh, *ol, *zh, *zl;
    float *gv;
    cudaGetSymbolAddress((void**)&xh, g_xh);
    cudaGetSymbolAddress((void**)&xl, g_xl);
    cudaGetSymbolAddress((void**)&wh, g_wh);
    cudaGetSymbolAddress((void**)&wl, g_wl);
    cudaGetSymbolAddress((void**)&oh, g_oh);
    cudaGetSymbolAddress((void**)&ol, g_ol);
    cudaGetSymbolAddress((void**)&zh, g_zh);
    cudaGetSymbolAddress((void**)&zl, g_zl);
    cudaGetSymbolAddress((void**)&gv, g_V);

    convert_all<<<3072, 256>>>(x, WQ, WK, WV, WO);

    // Fused QK-diag (bx 0..7) + V projection (bx 8..15): 512 CTAs
    qkv_fused<<<dim3(16, 32), 256, SMEM64>>>(xh, xl, wh, wl, gv);

    v_scan<<<dim3(32, 16), 256>>>();

    // Output projection (fp16x3)
    gemm64<<<dim3(8, 32), 256, SMEM64>>>(zh, zl, oh, ol, out);
}

// round 16
// speedup vs baseline: 1.6952x; 1.6952x over previous
#include <cuda_runtime.h>
#include <cuda_fp16.h>
#include <math.h>
#include <stdint.h>

#define SEQ     2048
#define DMODEL  512
#define NH      8
#define DH      64
#define BATCH   2
#define MTOT    4096

// ---------------- scratch (__device__ globals, allocation-free) -------------
__device__ __half g_xh[MTOT * DMODEL];
__device__ __half g_xl[MTOT * DMODEL];
__device__ __half g_wh[3 * DMODEL * DMODEL];   // [Wq;Wk;Wv] rows 0..1535 (hi)
__device__ __half g_wl[3 * DMODEL * DMODEL];   // lo used only for Wv range
__device__ __half g_oh[DMODEL * DMODEL];
__device__ __half g_ol[DMODEL * DMODEL];
__device__ float  g_V [MTOT * DMODEL];
__device__ __half g_zh[MTOT * DMODEL];
__device__ __half g_zl[MTOT * DMODEL];
__device__ float  g_sa[16 * SEQ];
__device__ float  g_sc[16 * SEQ];
__device__ float  g_cs[16 * 128 * 64];   // [bh][chunk16][dh] fine V sums
__device__ float  g_cb[16 * 16 * 64];    // [bh][mblk128][dh] coarse V sums

// ---------------------------------------------------------------------------
__device__ __forceinline__ uint32_t smem_u32(const void* p) {
    uint32_t a;
    asm("{ .reg .u64 t; cvta.to.shared.u64 t, %1; cvt.u32.u64 %0, t; }"
        : "=r"(a) : "l"(p));
    return a;
}

#define CPASYNC(d, s) \
    asm volatile("cp.async.cg.shared.global [%0], [%1], 16;" \
                 :: "r"(d), "l"(s) : "memory")

#define LDSM4(r, a) \
    asm volatile("ldmatrix.sync.aligned.m8n8.x4.shared.b16 {%0,%1,%2,%3}, [%4];" \
                 : "=r"((r)[0]), "=r"((r)[1]), "=r"((r)[2]), "=r"((r)[3]) \
                 : "r"(a))

#define MMA(d, a, b0, b1) \
    asm volatile("mma.sync.aligned.m16n8k16.row.col.f32.f16.f16.f32 " \
                 "{%0,%1,%2,%3},{%4,%5,%6,%7},{%8,%9},{%0,%1,%2,%3};" \
                 : "+f"((d)[0]), "+f"((d)[1]), "+f"((d)[2]), "+f"((d)[3]) \
                 : "r"((a)[0]), "r"((a)[1]), "r"((a)[2]), "r"((a)[3]), \
                   "r"(b0), "r"(b1))

// 128x64 BK=32 tiling, 3-stage pipeline
#define SROW2 40                         // 32 halves + 8 pad
#define A_MAT (128 * SROW2)              // halves
#define B_MAT (64 * SROW2)
#define STAGEH (2 * A_MAT + 2 * B_MAT)   // V/out stage (Ah,Al,Bh,Bl) halves
#define SMEM64 (3 * STAGEH * 2)          // 92160 B
#define STAGEQK (A_MAT + 2 * B_MAT)      // QK stage (A,BQ,BK) halves

// Batched fragment load for one kk (fp16x3 branch): 8 LDSM back-to-back
#define LDFRAG3(base, kkv, A0, A1, A2, A3, B0h, B0l, B1h, B1l) { \
    const uint32_t aH = (base) + a_row_off + (kkv) * 32; \
    const uint32_t aL = aH + A_MAT * 2; \
    LDSM4(A0, aH); \
    LDSM4(A1, aH + 16 * SROW2 * 2); \
    LDSM4(A2, aL); \
    LDSM4(A3, aL + 16 * SROW2 * 2); \
    const uint32_t bH = (base) + 2 * A_MAT * 2 + b_row_off + (kkv) * 32; \
    const uint32_t bL = bH + B_MAT * 2; \
    LDSM4(B0h, bH); \
    LDSM4(B0l, bL); \
    LDSM4(B1h, bH + 16 * SROW2 * 2); \
    LDSM4(B1l, bL + 16 * SROW2 * 2); \
}

// 24 MMAs of one kk (fp16x3 branch)
#define MMAS3(A0, A1, A2, A3, B0h, B0l, B1h, B1l) { \
    MMA(acc[0][0], A0, B0h[0], B0h[1]); \
    MMA(acc[1][0], A1, B0h[0], B0h[1]); \
    MMA(acc[0][1], A0, B0h[2], B0h[3]); \
    MMA(acc[1][1], A1, B0h[2], B0h[3]); \
    MMA(acc[0][2], A0, B1h[0], B1h[1]); \
    MMA(acc[1][2], A1, B1h[0], B1h[1]); \
    MMA(acc[0][3], A0, B1h[2], B1h[3]); \
    MMA(acc[1][3], A1, B1h[2], B1h[3]); \
    MMA(acc[0][0], A2, B0h[0], B0h[1]); \
    MMA(acc[1][0], A3, B0h[0], B0h[1]); \
    MMA(acc[0][1], A2, B0h[2], B0h[3]); \
    MMA(acc[1][1], A3, B0h[2], B0h[3]); \
    MMA(acc[0][2], A2, B1h[0], B1h[1]); \
    MMA(acc[1][2], A3, B1h[0], B1h[1]); \
    MMA(acc[0][3], A2, B1h[2], B1h[3]); \
    MMA(acc[1][3], A3, B1h[2], B1h[3]); \
    MMA(acc[0][0], A0, B0l[0], B0l[1]); \
    MMA(acc[1][0], A1, B0l[0], B0l[1]); \
    MMA(acc[0][1], A0, B0l[2], B0l[3]); \
    MMA(acc[1][1], A1, B0l[2], B0l[3]); \
    MMA(acc[0][2], A0, B1l[0], B1l[1]); \
    MMA(acc[1][2], A1, B1l[0], B1l[1]); \
    MMA(acc[0][3], A0, B1l[2], B1l[3]); \
    MMA(acc[1][3], A1, B1l[2], B1l[3]); \
}

// ---------------------------------------------------------------------------
// fp32 -> fp16 hi/lo conversion (lo skipped for Wq/Wk)
// ---------------------------------------------------------------------------
__global__ __launch_bounds__(256) void convert_all(
    const float* __restrict__ x,  const float* __restrict__ wq,
    const float* __restrict__ wk, const float* __restrict__ wv,
    const float* __restrict__ wo)
{
    int t = blockIdx.x * 256 + threadIdx.x;       // float4 index, 786432 total
    const float* src;
    __half *dh, *dl;
    int idx;
    bool wantLo = true;
    if (t < 524288)      { src = x;  dh = g_xh;          dl = g_xl;          idx = t; }
    else if (t < 589824) { src = wq; dh = g_wh;          dl = g_wl;          idx = t - 524288; wantLo = false; }
    else if (t < 655360) { src = wk; dh = g_wh + 262144; dl = g_wl + 262144; idx = t - 589824; wantLo = false; }
    else if (t < 720896) { src = wv; dh = g_wh + 524288; dl = g_wl + 524288; idx = t - 655360; }
    else                 { src = wo; dh = g_oh;          dl = g_ol;          idx = t - 720896; }

    float4 v = ((const float4*)src)[idx];
    __half h0 = __float2half_rn(v.x), h1 = __float2half_rn(v.y);
    __half h2 = __float2half_rn(v.z), h3 = __float2half_rn(v.w);
    __half2* ph = (__half2*)(dh + idx * 4);
    ph[0] = __halves2half2(h0, h1); ph[1] = __halves2half2(h2, h3);
    if (wantLo) {
        __half l0 = __float2half_rn(v.x - __half2float(h0));
        __half l1 = __float2half_rn(v.y - __half2float(h1));
        __half l2 = __float2half_rn(v.z - __half2float(h2));
        __half l3 = __float2half_rn(v.w - __half2float(h3));
        __half2* pl = (__half2*)(dl + idx * 4);
        pl[0] = __halves2half2(l0, l1); pl[1] = __halves2half2(l2, l3);
    }
}

// ---------------------------------------------------------------------------
// Fused QK-diag + V-projection. grid (16, 32), both 128x64/BK=32, 3-stage,
// one barrier per chunk, per-kk fragment batching, 2 CTAs/SM.
// ---------------------------------------------------------------------------
__global__ __launch_bounds__(256, 2) void qkv_fused(
    const __half* __restrict__ xh, const __half* __restrict__ xl,
    const __half* __restrict__ wh, const __half* __restrict__ wl,
    float* __restrict__ V)
{
    extern __shared__ __half sm[];
    const uint32_t sb = smem_u32(sm);
    const int tid = threadIdx.x;
    const int lane = tid & 31, wid = tid >> 5;
    const int wm = wid & 3, wn = wid >> 2;
    const int m0 = blockIdx.y * 128;

    const int lrA = tid >> 1, lpA = tid & 1;
    const int lrB = tid >> 2, lpB = tid & 3;
    const uint32_t dA = sb + (uint32_t)(lrA * SROW2 + lpA * 16) * 2;
    const uint32_t dB = sb + (uint32_t)(lrB * SROW2 + lpB * 8) * 2;

    const uint32_t a_row_off =
        (uint32_t)((wm * 32 + (lane & 15)) * SROW2) * 2 + (uint32_t)((lane >> 4) * 16);
    const int bn = wn * 32 + (lane & 7) + ((lane >> 4) << 3);
    const uint32_t b_row_off =
        (uint32_t)(bn * SROW2) * 2 + (uint32_t)(((lane >> 3) & 1) * 16);

    if (blockIdx.x < 8) {
        // ================= QK-diagonal branch (plain fp16) ==================
        const int n0 = blockIdx.x * 64;   // head = blockIdx.x
        const __half* gA = xh + (size_t)(m0 + lrA) * 512 + lpA * 16;
        const __half* gQ = wh + (size_t)(n0 + lrB) * 512 + lpB * 8;
        const __half* gK = wh + 512 * 512 + (size_t)(n0 + lrB) * 512 + lpB * 8;

#define LOADQK(c, s) { \
        const uint32_t soff = (uint32_t)(s) * (STAGEQK * 2); \
        const int ko = (c) * 32; \
        CPASYNC(dA + soff + 0,  gA + ko); \
        CPASYNC(dA + soff + 16, gA + ko + 8); \
        CPASYNC(dB + soff + A_MAT * 2, gQ + ko); \
        CPASYNC(dB + soff + A_MAT * 2 + B_MAT * 2, gK + ko); \
    }

        float aq[2][4][4], ak[2][4][4];
#pragma unroll
        for (int i = 0; i < 2; i++)
#pragma unroll
            for (int j = 0; j < 4; j++)
#pragma unroll
                for (int k = 0; k < 4; k++) { aq[i][j][k] = 0.0f; ak[i][j][k] = 0.0f; }

        LOADQK(0, 0);
        asm volatile("cp.async.commit_group;" ::: "memory");
        LOADQK(1, 1);
        asm volatile("cp.async.commit_group;" ::: "memory");

        for (int c = 0; c < 16; c++) {
            if (c < 15) {
                asm volatile("cp.async.wait_group 1;" ::: "memory");
            } else {
                asm volatile("cp.async.wait_group 0;" ::: "memory");
            }
            __syncthreads();
            if (c < 14) {
                LOADQK(c + 2, (c + 2) % 3);
                asm volatile("cp.async.commit_group;" ::: "memory");
            }

            const uint32_t base = sb + (uint32_t)(c % 3) * (STAGEQK * 2);
#pragma unroll
            for (int kk = 0; kk < 2; kk++) {
                uint32_t A0[4], A1[4], Bq0[4], Bk0[4], Bq1[4], Bk1[4];
                const uint32_t aA = base + a_row_off + kk * 32;
                LDSM4(A0, aA);
                LDSM4(A1, aA + 16 * SROW2 * 2);
                const uint32_t bQ = base + A_MAT * 2 + b_row_off + kk * 32;
                const uint32_t bK = bQ + B_MAT * 2;
                LDSM4(Bq0, bQ);
                LDSM4(Bk0, bK);
                LDSM4(Bq1, bQ + 16 * SROW2 * 2);
                LDSM4(Bk1, bK + 16 * SROW2 * 2);

                MMA(aq[0][0], A0, Bq0[0], Bq0[1]);
                MMA(aq[1][0], A1, Bq0[0], Bq0[1]);
                MMA(aq[0][1], A0, Bq0[2], Bq0[3]);
                MMA(aq[1][1], A1, Bq0[2], Bq0[3]);
                MMA(aq[0][2], A0, Bq1[0], Bq1[1]);
                MMA(aq[1][2], A1, Bq1[0], Bq1[1]);
                MMA(aq[0][3], A0, Bq1[2], Bq1[3]);
                MMA(aq[1][3], A1, Bq1[2], Bq1[3]);
                MMA(ak[0][0], A0, Bk0[0], Bk0[1]);
                MMA(ak[1][0], A1, Bk0[0], Bk0[1]);
                MMA(ak[0][1], A0, Bk0[2], Bk0[3]);
                MMA(ak[1][1], A1, Bk0[2], Bk0[3]);
                MMA(ak[0][2], A0, Bk1[0], Bk1[1]);
                MMA(ak[1][2], A1, Bk1[0], Bk1[1]);
                MMA(ak[0][3], A0, Bk1[2], Bk1[3]);
                MMA(ak[1][3], A1, Bk1[2], Bk1[3]);
            }
        }
        __syncthreads();

        float pj[4];
#pragma unroll
        for (int j = 0; j < 4; j++) {
            const int mi = j >> 1, o = (j & 1) * 2;
            float p = 0.0f;
#pragma unroll
            for (int ni = 0; ni < 4; ni++)
                p += aq[mi][ni][o] * ak[mi][ni][o]
                   + aq[mi][ni][o + 1] * ak[mi][ni][o + 1];
            p += __shfl_xor_sync(0xFFFFFFFF, p, 1);
            p += __shfl_xor_sync(0xFFFFFFFF, p, 2);
            pj[j] = p;
        }

        float* buf = (float*)sm;   // 128 floats
        if (wn == 1 && (lane & 3) == 0) {
#pragma unroll
            for (int j = 0; j < 4; j++)
                buf[(wm * 4 + j) * 8 + (lane >> 2)] = pj[j];
        }
        __syncthreads();
        if (wn == 0 && (lane & 3) == 0) {
            const int h = blockIdx.x;
#pragma unroll
            for (int j = 0; j < 4; j++) {
                float p = pj[j] + buf[(wm * 4 + j) * 8 + (lane >> 2)];
                const int m = m0 + wm * 32 + (lane >> 2) + (j >> 1) * 16 + (j & 1) * 8;
                const int b = m >> 11, q = m & 2047;
                float sd = p * 0.125f;
                int cnt = SEQ - 1 - q;
                float mx = (cnt > 0) ? fmaxf(sd, 0.0f) : sd;
                float ed = expf(sd - mx);
                float eo = (cnt > 0) ? expf(-mx) : 0.0f;
                float Z = ed + (float)cnt * eo;
                g_sa[(b * 8 + h) * SEQ + q] = ed / Z;
                g_sc[(b * 8 + h) * SEQ + q] = eo / Z;
            }
        }
    } else {
        // ================= V branch (fp16x3) ================================
        const int n0 = (blockIdx.x - 8) * 64;
        const __half* gAh = xh + (size_t)(m0 + lrA) * 512 + lpA * 16;
        const __half* gAl = xl + (size_t)(m0 + lrA) * 512 + lpA * 16;
        const __half* gBh = wh + 1024 * 512 + (size_t)(n0 + lrB) * 512 + lpB * 8;
        const __half* gBl = wl + 1024 * 512 + (size_t)(n0 + lrB) * 512 + lpB * 8;

#define LOADCH64(c, s) { \
        const uint32_t soff = (uint32_t)(s) * (STAGEH * 2); \
        const int ko = (c) * 32; \
        CPASYNC(dA + soff + 0 * A_MAT * 2 + 0,  gAh + ko); \
        CPASYNC(dA + soff + 0 * A_MAT * 2 + 16, gAh + ko + 8); \
        CPASYNC(dA + soff + 1 * A_MAT * 2 + 0,  gAl + ko); \
        CPASYNC(dA + soff + 1 * A_MAT * 2 + 16, gAl + ko + 8); \
        CPASYNC(dB + soff + 2 * A_MAT * 2 + 0,  gBh + ko); \
        CPASYNC(dB + soff + 2 * A_MAT * 2 + B_MAT * 2, gBl + ko); \
    }

        float acc[2][4][4];
#pragma unroll
        for (int i = 0; i < 2; i++)
#pragma unroll
            for (int j = 0; j < 4; j++)
#pragma unroll
                for (int k = 0; k < 4; k++) acc[i][j][k] = 0.0f;

        LOADCH64(0, 0);
        asm volatile("cp.async.commit_group;" ::: "memory");
        LOADCH64(1, 1);
        asm volatile("cp.async.commit_group;" ::: "memory");

        for (int c = 0; c < 16; c++) {
            if (c < 15) {
                asm volatile("cp.async.wait_group 1;" ::: "memory");
            } else {
                asm volatile("cp.async.wait_group 0;" ::: "memory");
            }
            __syncthreads();
            if (c < 14) {
                LOADCH64(c + 2, (c + 2) % 3);
                asm volatile("cp.async.commit_group;" ::: "memory");
            }

            const uint32_t base = sb + (uint32_t)(c % 3) * (STAGEH * 2);
#pragma unroll
            for (int kk = 0; kk < 2; kk++) {
                uint32_t A0[4], A1[4], A2[4], A3[4];
                uint32_t B0h[4], B0l[4], B1h[4], B1l[4];
                LDFRAG3(base, kk, A0, A1, A2, A3, B0h, B0l, B1h, B1l);
                MMAS3(A0, A1, A2, A3, B0h, B0l, B1h, B1l);
            }
        }
        __syncthreads();

        // Epilogue: fp32 V store
        const int r0 = m0 + wm * 32 + (lane >> 2);
        const int cb2 = n0 + wn * 32 + (lane & 3) * 2;
#pragma unroll
        for (int mi = 0; mi < 2; mi++) {
            const int r = r0 + mi * 16;
#pragma unroll
            for (int ni = 0; ni < 4; ni++) {
                const int cg = cb2 + ni * 8;
                *(float2*)&V[(size_t)r * 512 + cg] =
                    make_float2(acc[mi][ni][0], acc[mi][ni][1]);
                *(float2*)&V[(size_t)(r + 8) * 512 + cg] =
                    make_float2(acc[mi][ni][2], acc[mi][ni][3]);
            }
        }

        // Fine 16-row chunk sums + coarse 128-row sums
        const int b = m0 >> 11;
        const int c16 = ((m0 & 2047) >> 4) + wm * 2;
        const int h = n0 >> 6;
        const int bh = b * 8 + h;
        float* cbuf = (float*)sm;   // [4 wm][64 dh]
#pragma unroll
        for (int ni = 0; ni < 4; ni++) {
            float t0 = 0.0f, t1 = 0.0f;
#pragma unroll
            for (int mi = 0; mi < 2; mi++) {
                float s0 = acc[mi][ni][0] + acc[mi][ni][2];
                float s1 = acc[mi][ni][1] + acc[mi][ni][3];
#pragma unroll
                for (int st = 4; st < 32; st <<= 1) {
                    s0 += __shfl_xor_sync(0xFFFFFFFF, s0, st);
                    s1 += __shfl_xor_sync(0xFFFFFFFF, s1, st);
                }
                if (lane < 4) {
                    const int dh = wn * 32 + (lane << 1) + ni * 8;
                    *(float2*)&g_cs[((size_t)bh * 128 + c16 + mi) * 64 + dh] =
                        make_float2(s0, s1);
                }
                t0 += s0; t1 += s1;
            }
            if (lane < 4) {
                const int dh = wn * 32 + (lane << 1) + ni * 8;
                cbuf[wm * 64 + dh]     = t0;
                cbuf[wm * 64 + dh + 1] = t1;
            }
        }
        __syncthreads();
        if (tid < 64) {
            const int mblk = (m0 & 2047) >> 7;   // 0..15
            g_cb[((size_t)bh * 16 + mblk) * 64 + tid] =
                cbuf[tid] + cbuf[64 + tid] + cbuf[128 + tid] + cbuf[192 + tid];
        }
    }
}

// ---------------------------------------------------------------------------
// fp16x3 GEMM, 128x64/BK=32, 3-stage, per-kk fragment batching — out proj.
// ---------------------------------------------------------------------------
__global__ __launch_bounds__(256, 2) void gemm64(
    const __half* __restrict__ Ah, const __half* __restrict__ Al,
    const __half* __restrict__ Bh, const __half* __restrict__ Bl,
    float* __restrict__ C)
{
    extern __shared__ __half sm[];
    const uint32_t sb = smem_u32(sm);
    const int tid = threadIdx.x;
    const int lane = tid & 31, wid = tid >> 5;
    const int wm = wid & 3, wn = wid >> 2;
    const int n0 = blockIdx.x * 64, m0 = blockIdx.y * 128;

    const int lrA = tid >> 1, lpA = tid & 1;
    const int lrB = tid >> 2, lpB = tid & 3;
    const __half* gAh = Ah + (size_t)(m0 + lrA) * 512 + lpA * 16;
    const __half* gAl = Al + (size_t)(m0 + lrA) * 512 + lpA * 16;
    const __half* gBh = Bh + (size_t)(n0 + lrB) * 512 + lpB * 8;
    const __half* gBl = Bl + (size_t)(n0 + lrB) * 512 + lpB * 8;
    const uint32_t dA = sb + (uint32_t)(lrA * SROW2 + lpA * 16) * 2;
    const uint32_t dB = sb + (uint32_t)(lrB * SROW2 + lpB * 8) * 2;

#define LOADCHO(c, s) { \
        const uint32_t soff = (uint32_t)(s) * (STAGEH * 2); \
        const int ko = (c) * 32; \
        CPASYNC(dA + soff + 0 * A_MAT * 2 + 0,  gAh + ko); \
        CPASYNC(dA + soff + 0 * A_MAT * 2 + 16, gAh + ko + 8); \
        CPASYNC(dA + soff + 1 * A_MAT * 2 + 0,  gAl + ko); \
        CPASYNC(dA + soff + 1 * A_MAT * 2 + 16, gAl + ko + 8); \
        CPASYNC(dB + soff + 2 * A_MAT * 2 + 0,  gBh + ko); \
        CPASYNC(dB + soff + 2 * A_MAT * 2 + B_MAT * 2, gBl + ko); \
    }

    float acc[2][4][4];
#pragma unroll
    for (int i = 0; i < 2; i++)
#pragma unroll
        for (int j = 0; j < 4; j++)
#pragma unroll
            for (int k = 0; k < 4; k++) acc[i][j][k] = 0.0f;

    LOADCHO(0, 0);
    asm volatile("cp.async.commit_group;" ::: "memory");
    LOADCHO(1, 1);
    asm volatile("cp.async.commit_group;" ::: "memory");

    const uint32_t a_row_off =
        (uint32_t)((wm * 32 + (lane & 15)) * SROW2) * 2 + (uint32_t)((lane >> 4) * 16);
    const int bn = wn * 32 + (lane & 7) + ((lane >> 4) << 3);
    const uint32_t b_row_off =
        (uint32_t)(bn * SROW2) * 2 + (uint32_t)(((lane >> 3) & 1) * 16);

    for (int c = 0; c < 16; c++) {
        if (c < 15) {
            asm volatile("cp.async.wait_group 1;" ::: "memory");
        } else {
            asm volatile("cp.async.wait_group 0;" ::: "memory");
        }
        __syncthreads();
        if (c < 14) {
            LOADCHO(c + 2, (c + 2) % 3);
            asm volatile("cp.async.commit_group;" ::: "memory");
        }

        const uint32_t base = sb + (uint32_t)(c % 3) * (STAGEH * 2);
#pragma unroll
        for (int kk = 0; kk < 2; kk++) {
            uint32_t A0[4], A1[4], A2[4], A3[4];
            uint32_t B0h[4], B0l[4], B1h[4], B1l[4];
            LDFRAG3(base, kk, A0, A1, A2, A3, B0h, B0l, B1h, B1l);
            MMAS3(A0, A1, A2, A3, B0h, B0l, B1h, B1l);
        }
    }

    const int r0 = m0 + wm * 32 + (lane >> 2);
    const int cb = n0 + wn * 32 + (lane & 3) * 2;
#pragma unroll
    for (int mi = 0; mi < 2; mi++) {
        const int r = r0 + mi * 16;
#pragma unroll
        for (int ni = 0; ni < 4; ni++) {
            const int cg = cb + ni * 8;
            *(float2*)&C[(size_t)r * 512 + cg] =
                make_float2(acc[mi][ni][0], acc[mi][ni][1]);
            *(float2*)&C[(size_t)(r + 8) * 512 + cg] =
                make_float2(acc[mi][ni][2], acc[mi][ni][3]);
        }
    }
}

// ---------------------------------------------------------------------------
// Scan: z[q] = a_q*v[q] + c_q*suffix_{p>q} v[p]. Run-in from coarse + fine sums.
// ---------------------------------------------------------------------------
__global__ __launch_bounds__(256) void v_scan()
{
    int bh = blockIdx.y;
    int chunk = blockIdx.x * 4 + (threadIdx.x >> 6);   // 0..127
    int dh = threadIdx.x & 63;
    int b = bh >> 3, h = bh & 7;
    const int q0 = chunk * 16;

    // Run-in: coarse 128-row blocks after this chunk's block + fine chunks
    const int cbk = chunk >> 3;
    float run = 0.0f;
    const float* cbp = g_cb + ((size_t)bh * 16) * 64 + dh;
    for (int j = cbk + 1; j < 16; j++) run += cbp[(size_t)j * 64];
    const float* csp = g_cs + ((size_t)bh * 128) * 64 + dh;
    const int cfEnd = (cbk + 1) << 3;
    for (int cf = chunk + 1; cf < cfEnd; cf++) run += csp[(size_t)cf * 64];

    // Batch all loads up front
    const float* vbase = g_V + (size_t)(b * SEQ + q0) * DMODEL + h * DH + dh;
    float v[16];
#pragma unroll
    for (int i = 0; i < 16; i++) v[i] = vbase[i * DMODEL];

    float wa[16], wc[16];
    const float* sa = g_sa + bh * SEQ + q0;
    const float* sc = g_sc + bh * SEQ + q0;
#pragma unroll
    for (int i = 0; i < 16; i++) { wa[i] = sa[i]; wc[i] = sc[i]; }

    __half* zhb = g_zh + (size_t)(b * SEQ + q0) * DMODEL + h * DH + dh;
    __half* zlb = g_zl + (size_t)(b * SEQ + q0) * DMODEL + h * DH + dh;
#pragma unroll
    for (int i = 15; i >= 0; i--) {
        float z = wa[i] * v[i] + wc[i] * run;
        __half zh = __float2half_rn(z);
        zhb[i * DMODEL] = zh;
        zlb[i * DMODEL] = __float2half_rn(z - __half2float(zh));
        run += v[i];
    }
}

// ---------------------------------------------------------------------------
extern "C" void kernel_launch(void* const* d_in, const int* in_sizes, int n_in,
                              void* d_out, int out_size)
{
    const float* x  = (const float*)d_in[0];
    const float* WQ = (const float*)d_in[1];
    const float* WK = (const float*)d_in[2];
    const float* WV = (const float*)d_in[3];
    const float* WO = (const float*)d_in[4];
    float* out = (float*)d_out;

    cudaFuncSetAttribute(qkv_fused, cudaFuncAttributeMaxDynamicSharedMemorySize,
                         SMEM64);
    cudaFuncSetAttribute(gemm64, cudaFuncAttributeMaxDynamicSharedMemorySize,
                         SMEM64);

    __half *xh, *xl, *wh, *wl, *oh, *ol, *zh, *zl;
    float *gv;
    cudaGetSymbolAddress((void**)&xh, g_xh);
    cudaGetSymbolAddress((void**)&xl, g_xl);
    cudaGetSymbolAddress((void**)&wh, g_wh);
    cudaGetSymbolAddress((void**)&wl, g_wl);
    cudaGetSymbolAddress((void**)&oh, g_oh);
    cudaGetSymbolAddress((void**)&ol, g_ol);
    cudaGetSymbolAddress((void**)&zh, g_zh);
    cudaGetSymbolAddress((void**)&zl, g_zl);
    cudaGetSymbolAddress((void**)&gv, g_V);

    convert_all<<<3072, 256>>>(x, WQ, WK, WV, WO);

    // Fused QK-diag (bx 0..7) + V projection (bx 8..15): 512 CTAs
    qkv_fused<<<dim3(16, 32), 256, SMEM64>>>(xh, xl, wh, wl, gv);

    v_scan<<<dim3(32, 16), 256>>>();

    // Output projection (fp16x3)
    gemm64<<<dim3(8, 32), 256, SMEM64>>>(zh, zl, oh, ol, out);
}

// round 17
// speedup vs baseline: 1.8664x; 1.1010x over previous
#include <cuda_runtime.h>
#include <cuda_fp16.h>
#include <math.h>
#include <stdint.h>

#define SEQ     2048
#define DMODEL  512
#define NH      8
#define DH      64
#define BATCH   2
#define MTOT    4096

// ---------------- scratch (__device__ globals, allocation-free) -------------
__device__ __half g_xh[MTOT * DMODEL];
__device__ __half g_xl[MTOT * DMODEL];
__device__ __half g_wh[3 * DMODEL * DMODEL];   // [Wq;Wk;Wv] rows 0..1535 (hi)
__device__ __half g_wl[3 * DMODEL * DMODEL];   // lo used only for Wv range
__device__ __half g_oh[DMODEL * DMODEL];
__device__ __half g_ol[DMODEL * DMODEL];
__device__ float  g_V [MTOT * DMODEL];
__device__ __half g_zh[MTOT * DMODEL];
__device__ float  g_sa[16 * SEQ];
__device__ float  g_sc[16 * SEQ];
__device__ float  g_cs[16 * 128 * 64];   // [bh][chunk16][dh] fine V sums
__device__ float  g_cb[16 * 16 * 64];    // [bh][mblk128][dh] coarse V sums

// ---------------------------------------------------------------------------
__device__ __forceinline__ uint32_t smem_u32(const void* p) {
    uint32_t a;
    asm("{ .reg .u64 t; cvta.to.shared.u64 t, %1; cvt.u32.u64 %0, t; }"
        : "=r"(a) : "l"(p));
    return a;
}

#define CPASYNC(d, s) \
    asm volatile("cp.async.cg.shared.global [%0], [%1], 16;" \
                 :: "r"(d), "l"(s) : "memory")

#define LDSM4(r, a) \
    asm volatile("ldmatrix.sync.aligned.m8n8.x4.shared.b16 {%0,%1,%2,%3}, [%4];" \
                 : "=r"((r)[0]), "=r"((r)[1]), "=r"((r)[2]), "=r"((r)[3]) \
                 : "r"(a))

#define MMA(d, a, b0, b1) \
    asm volatile("mma.sync.aligned.m16n8k16.row.col.f32.f16.f16.f32 " \
                 "{%0,%1,%2,%3},{%4,%5,%6,%7},{%8,%9},{%0,%1,%2,%3};" \
                 : "+f"((d)[0]), "+f"((d)[1]), "+f"((d)[2]), "+f"((d)[3]) \
                 : "r"((a)[0]), "r"((a)[1]), "r"((a)[2]), "r"((a)[3]), \
                   "r"(b0), "r"(b1))

// 128x64 BK=32 tiling, 3-stage pipeline
#define SROW2 40                         // 32 halves + 8 pad
#define A_MAT (128 * SROW2)              // halves
#define B_MAT (64 * SROW2)
#define STAGEH (2 * A_MAT + 2 * B_MAT)   // V stage (Ah,Al,Bh,Bl) halves
#define SMEM64 (3 * STAGEH * 2)          // 92160 B
#define STAGEQK (A_MAT + 2 * B_MAT)      // QK stage (A,BQ,BK) halves
#define STAGEO  (A_MAT + 2 * B_MAT)      // out stage (A,Bh,Bl) halves
#define SMEMO   (3 * STAGEO * 2)         // 61440 B

// Batched fragment load for one kk (fp16x3 branch): 8 LDSM back-to-back
#define LDFRAG3(base, kkv, A0, A1, A2, A3, B0h, B0l, B1h, B1l) { \
    const uint32_t aH = (base) + a_row_off + (kkv) * 32; \
    const uint32_t aL = aH + A_MAT * 2; \
    LDSM4(A0, aH); \
    LDSM4(A1, aH + 16 * SROW2 * 2); \
    LDSM4(A2, aL); \
    LDSM4(A3, aL + 16 * SROW2 * 2); \
    const uint32_t bH = (base) + 2 * A_MAT * 2 + b_row_off + (kkv) * 32; \
    const uint32_t bL = bH + B_MAT * 2; \
    LDSM4(B0h, bH); \
    LDSM4(B0l, bL); \
    LDSM4(B1h, bH + 16 * SROW2 * 2); \
    LDSM4(B1l, bL + 16 * SROW2 * 2); \
}

// 24 MMAs of one kk (fp16x3 branch)
#define MMAS3(A0, A1, A2, A3, B0h, B0l, B1h, B1l) { \
    MMA(acc[0][0], A0, B0h[0], B0h[1]); \
    MMA(acc[1][0], A1, B0h[0], B0h[1]); \
    MMA(acc[0][1], A0, B0h[2], B0h[3]); \
    MMA(acc[1][1], A1, B0h[2], B0h[3]); \
    MMA(acc[0][2], A0, B1h[0], B1h[1]); \
    MMA(acc[1][2], A1, B1h[0], B1h[1]); \
    MMA(acc[0][3], A0, B1h[2], B1h[3]); \
    MMA(acc[1][3], A1, B1h[2], B1h[3]); \
    MMA(acc[0][0], A2, B0h[0], B0h[1]); \
    MMA(acc[1][0], A3, B0h[0], B0h[1]); \
    MMA(acc[0][1], A2, B0h[2], B0h[3]); \
    MMA(acc[1][1], A3, B0h[2], B0h[3]); \
    MMA(acc[0][2], A2, B1h[0], B1h[1]); \
    MMA(acc[1][2], A3, B1h[0], B1h[1]); \
    MMA(acc[0][3], A2, B1h[2], B1h[3]); \
    MMA(acc[1][3], A3, B1h[2], B1h[3]); \
    MMA(acc[0][0], A0, B0l[0], B0l[1]); \
    MMA(acc[1][0], A1, B0l[0], B0l[1]); \
    MMA(acc[0][1], A0, B0l[2], B0l[3]); \
    MMA(acc[1][1], A1, B0l[2], B0l[3]); \
    MMA(acc[0][2], A0, B1l[0], B1l[1]); \
    MMA(acc[1][2], A1, B1l[0], B1l[1]); \
    MMA(acc[0][3], A0, B1l[2], B1l[3]); \
    MMA(acc[1][3], A1, B1l[2], B1l[3]); \
}

// ---------------------------------------------------------------------------
// fp32 -> fp16 hi/lo conversion (lo skipped for Wq/Wk)
// ---------------------------------------------------------------------------
__global__ __launch_bounds__(256) void convert_all(
    const float* __restrict__ x,  const float* __restrict__ wq,
    const float* __restrict__ wk, const float* __restrict__ wv,
    const float* __restrict__ wo)
{
    int t = blockIdx.x * 256 + threadIdx.x;       // float4 index, 786432 total
    const float* src;
    __half *dh, *dl;
    int idx;
    bool wantLo = true;
    if (t < 524288)      { src = x;  dh = g_xh;          dl = g_xl;          idx = t; }
    else if (t < 589824) { src = wq; dh = g_wh;          dl = g_wh;          idx = t - 524288; wantLo = false; }
    else if (t < 655360) { src = wk; dh = g_wh + 262144; dl = g_wh; idx = t - 589824; wantLo = false; }
    else if (t < 720896) { src = wv; dh = g_wh + 524288; dl = g_wl + 524288; idx = t - 655360; }
    else                 { src = wo; dh = g_oh;          dl = g_ol;          idx = t - 720896; }

    float4 v = ((const float4*)src)[idx];
    __half h0 = __float2half_rn(v.x), h1 = __float2half_rn(v.y);
    __half h2 = __float2half_rn(v.z), h3 = __float2half_rn(v.w);
    __half2* ph = (__half2*)(dh + idx * 4);
    ph[0] = __halves2half2(h0, h1); ph[1] = __halves2half2(h2, h3);
    if (wantLo) {
        __half l0 = __float2half_rn(v.x - __half2float(h0));
        __half l1 = __float2half_rn(v.y - __half2float(h1));
        __half l2 = __float2half_rn(v.z - __half2float(h2));
        __half l3 = __float2half_rn(v.w - __half2float(h3));
        __half2* pl = (__half2*)(dl + idx * 4);
        pl[0] = __halves2half2(l0, l1); pl[1] = __halves2half2(l2, l3);
    }
}

// ---------------------------------------------------------------------------
// Fused QK-diag + V-projection. grid (16, 32), both 128x64/BK=32, 3-stage,
// one barrier per chunk, per-kk fragment batching, 2 CTAs/SM.
// ---------------------------------------------------------------------------
__global__ __launch_bounds__(256, 2) void qkv_fused(
    const __half* __restrict__ xh, const __half* __restrict__ xl,
    const __half* __restrict__ wh, const __half* __restrict__ wl,
    float* __restrict__ V)
{
    extern __shared__ __half sm[];
    const uint32_t sb = smem_u32(sm);
    const int tid = threadIdx.x;
    const int lane = tid & 31, wid = tid >> 5;
    const int wm = wid & 3, wn = wid >> 2;
    const int m0 = blockIdx.y * 128;

    const int lrA = tid >> 1, lpA = tid & 1;
    const int lrB = tid >> 2, lpB = tid & 3;
    const uint32_t dA = sb + (uint32_t)(lrA * SROW2 + lpA * 16) * 2;
    const uint32_t dB = sb + (uint32_t)(lrB * SROW2 + lpB * 8) * 2;

    const uint32_t a_row_off =
        (uint32_t)((wm * 32 + (lane & 15)) * SROW2) * 2 + (uint32_t)((lane >> 4) * 16);
    const int bn = wn * 32 + (lane & 7) + ((lane >> 4) << 3);
    const uint32_t b_row_off =
        (uint32_t)(bn * SROW2) * 2 + (uint32_t)(((lane >> 3) & 1) * 16);

    if (blockIdx.x < 8) {
        // ================= QK-diagonal branch (plain fp16) ==================
        const int n0 = blockIdx.x * 64;   // head = blockIdx.x
        const __half* gA = xh + (size_t)(m0 + lrA) * 512 + lpA * 16;
        const __half* gQ = wh + (size_t)(n0 + lrB) * 512 + lpB * 8;
        const __half* gK = wh + 512 * 512 + (size_t)(n0 + lrB) * 512 + lpB * 8;

#define LOADQK(c, s) { \
        const uint32_t soff = (uint32_t)(s) * (STAGEQK * 2); \
        const int ko = (c) * 32; \
        CPASYNC(dA + soff + 0,  gA + ko); \
        CPASYNC(dA + soff + 16, gA + ko + 8); \
        CPASYNC(dB + soff + A_MAT * 2, gQ + ko); \
        CPASYNC(dB + soff + A_MAT * 2 + B_MAT * 2, gK + ko); \
    }

        float aq[2][4][4], ak[2][4][4];
#pragma unroll
        for (int i = 0; i < 2; i++)
#pragma unroll
            for (int j = 0; j < 4; j++)
#pragma unroll
                for (int k = 0; k < 4; k++) { aq[i][j][k] = 0.0f; ak[i][j][k] = 0.0f; }

        LOADQK(0, 0);
        asm volatile("cp.async.commit_group;" ::: "memory");
        LOADQK(1, 1);
        asm volatile("cp.async.commit_group;" ::: "memory");

        for (int c = 0; c < 16; c++) {
            if (c < 15) {
                asm volatile("cp.async.wait_group 1;" ::: "memory");
            } else {
                asm volatile("cp.async.wait_group 0;" ::: "memory");
            }
            __syncthreads();
            if (c < 14) {
                LOADQK(c + 2, (c + 2) % 3);
                asm volatile("cp.async.commit_group;" ::: "memory");
            }

            const uint32_t base = sb + (uint32_t)(c % 3) * (STAGEQK * 2);
#pragma unroll
            for (int kk = 0; kk < 2; kk++) {
                uint32_t A0[4], A1[4], Bq0[4], Bk0[4], Bq1[4], Bk1[4];
                const uint32_t aA = base + a_row_off + kk * 32;
                LDSM4(A0, aA);
                LDSM4(A1, aA + 16 * SROW2 * 2);
                const uint32_t bQ = base + A_MAT * 2 + b_row_off + kk * 32;
                const uint32_t bK = bQ + B_MAT * 2;
                LDSM4(Bq0, bQ);
                LDSM4(Bk0, bK);
                LDSM4(Bq1, bQ + 16 * SROW2 * 2);
                LDSM4(Bk1, bK + 16 * SROW2 * 2);

                MMA(aq[0][0], A0, Bq0[0], Bq0[1]);
                MMA(aq[1][0], A1, Bq0[0], Bq0[1]);
                MMA(aq[0][1], A0, Bq0[2], Bq0[3]);
                MMA(aq[1][1], A1, Bq0[2], Bq0[3]);
                MMA(aq[0][2], A0, Bq1[0], Bq1[1]);
                MMA(aq[1][2], A1, Bq1[0], Bq1[1]);
                MMA(aq[0][3], A0, Bq1[2], Bq1[3]);
                MMA(aq[1][3], A1, Bq1[2], Bq1[3]);
                MMA(ak[0][0], A0, Bk0[0], Bk0[1]);
                MMA(ak[1][0], A1, Bk0[0], Bk0[1]);
                MMA(ak[0][1], A0, Bk0[2], Bk0[3]);
                MMA(ak[1][1], A1, Bk0[2], Bk0[3]);
                MMA(ak[0][2], A0, Bk1[0], Bk1[1]);
                MMA(ak[1][2], A1, Bk1[0], Bk1[1]);
                MMA(ak[0][3], A0, Bk1[2], Bk1[3]);
                MMA(ak[1][3], A1, Bk1[2], Bk1[3]);
            }
        }
        __syncthreads();

        float pj[4];
#pragma unroll
        for (int j = 0; j < 4; j++) {
            const int mi = j >> 1, o = (j & 1) * 2;
            float p = 0.0f;
#pragma unroll
            for (int ni = 0; ni < 4; ni++)
                p += aq[mi][ni][o] * ak[mi][ni][o]
                   + aq[mi][ni][o + 1] * ak[mi][ni][o + 1];
            p += __shfl_xor_sync(0xFFFFFFFF, p, 1);
            p += __shfl_xor_sync(0xFFFFFFFF, p, 2);
            pj[j] = p;
        }

        float* buf = (float*)sm;   // 128 floats
        if (wn == 1 && (lane & 3) == 0) {
#pragma unroll
            for (int j = 0; j < 4; j++)
                buf[(wm * 4 + j) * 8 + (lane >> 2)] = pj[j];
        }
        __syncthreads();
        if (wn == 0 && (lane & 3) == 0) {
            const int h = blockIdx.x;
#pragma unroll
            for (int j = 0; j < 4; j++) {
                float p = pj[j] + buf[(wm * 4 + j) * 8 + (lane >> 2)];
                const int m = m0 + wm * 32 + (lane >> 2) + (j >> 1) * 16 + (j & 1) * 8;
                const int b = m >> 11, q = m & 2047;
                float sd = p * 0.125f;
                int cnt = SEQ - 1 - q;
                float mx = (cnt > 0) ? fmaxf(sd, 0.0f) : sd;
                float ed = expf(sd - mx);
                float eo = (cnt > 0) ? expf(-mx) : 0.0f;
                float Z = ed + (float)cnt * eo;
                g_sa[(b * 8 + h) * SEQ + q] = ed / Z;
                g_sc[(b * 8 + h) * SEQ + q] = eo / Z;
            }
        }
    } else {
        // ================= V branch (fp16x3) ================================
        const int n0 = (blockIdx.x - 8) * 64;
        const __half* gAh = xh + (size_t)(m0 + lrA) * 512 + lpA * 16;
        const __half* gAl = xl + (size_t)(m0 + lrA) * 512 + lpA * 16;
        const __half* gBh = wh + 1024 * 512 + (size_t)(n0 + lrB) * 512 + lpB * 8;
        const __half* gBl = wl + 1024 * 512 + (size_t)(n0 + lrB) * 512 + lpB * 8;

#define LOADCH64(c, s) { \
        const uint32_t soff = (uint32_t)(s) * (STAGEH * 2); \
        const int ko = (c) * 32; \
        CPASYNC(dA + soff + 0 * A_MAT * 2 + 0,  gAh + ko); \
        CPASYNC(dA + soff + 0 * A_MAT * 2 + 16, gAh + ko + 8); \
        CPASYNC(dA + soff + 1 * A_MAT * 2 + 0,  gAl + ko); \
        CPASYNC(dA + soff + 1 * A_MAT * 2 + 16, gAl + ko + 8); \
        CPASYNC(dB + soff + 2 * A_MAT * 2 + 0,  gBh + ko); \
        CPASYNC(dB + soff + 2 * A_MAT * 2 + B_MAT * 2, gBl + ko); \
    }

        float acc[2][4][4];
#pragma unroll
        for (int i = 0; i < 2; i++)
#pragma unroll
            for (int j = 0; j < 4; j++)
#pragma unroll
                for (int k = 0; k < 4; k++) acc[i][j][k] = 0.0f;

        LOADCH64(0, 0);
        asm volatile("cp.async.commit_group;" ::: "memory");
        LOADCH64(1, 1);
        asm volatile("cp.async.commit_group;" ::: "memory");

        for (int c = 0; c < 16; c++) {
            if (c < 15) {
                asm volatile("cp.async.wait_group 1;" ::: "memory");
            } else {
                asm volatile("cp.async.wait_group 0;" ::: "memory");
            }
            __syncthreads();
            if (c < 14) {
                LOADCH64(c + 2, (c + 2) % 3);
                asm volatile("cp.async.commit_group;" ::: "memory");
            }

            const uint32_t base = sb + (uint32_t)(c % 3) * (STAGEH * 2);
#pragma unroll
            for (int kk = 0; kk < 2; kk++) {
                uint32_t A0[4], A1[4], A2[4], A3[4];
                uint32_t B0h[4], B0l[4], B1h[4], B1l[4];
                LDFRAG3(base, kk, A0, A1, A2, A3, B0h, B0l, B1h, B1l);
                MMAS3(A0, A1, A2, A3, B0h, B0l, B1h, B1l);
            }
        }
        __syncthreads();

        // Epilogue: fp32 V store
        const int r0 = m0 + wm * 32 + (lane >> 2);
        const int cb2 = n0 + wn * 32 + (lane & 3) * 2;
#pragma unroll
        for (int mi = 0; mi < 2; mi++) {
            const int r = r0 + mi * 16;
#pragma unroll
            for (int ni = 0; ni < 4; ni++) {
                const int cg = cb2 + ni * 8;
                *(float2*)&V[(size_t)r * 512 + cg] =
                    make_float2(acc[mi][ni][0], acc[mi][ni][1]);
                *(float2*)&V[(size_t)(r + 8) * 512 + cg] =
                    make_float2(acc[mi][ni][2], acc[mi][ni][3]);
            }
        }

        // Fine 16-row chunk sums + coarse 128-row sums
        const int b = m0 >> 11;
        const int c16 = ((m0 & 2047) >> 4) + wm * 2;
        const int h = n0 >> 6;
        const int bh = b * 8 + h;
        float* cbuf = (float*)sm;   // [4 wm][64 dh]
#pragma unroll
        for (int ni = 0; ni < 4; ni++) {
            float t0 = 0.0f, t1 = 0.0f;
#pragma unroll
            for (int mi = 0; mi < 2; mi++) {
                float s0 = acc[mi][ni][0] + acc[mi][ni][2];
                float s1 = acc[mi][ni][1] + acc[mi][ni][3];
#pragma unroll
                for (int st = 4; st < 32; st <<= 1) {
                    s0 += __shfl_xor_sync(0xFFFFFFFF, s0, st);
                    s1 += __shfl_xor_sync(0xFFFFFFFF, s1, st);
                }
                if (lane < 4) {
                    const int dh = wn * 32 + (lane << 1) + ni * 8;
                    *(float2*)&g_cs[((size_t)bh * 128 + c16 + mi) * 64 + dh] =
                        make_float2(s0, s1);
                }
                t0 += s0; t1 += s1;
            }
            if (lane < 4) {
                const int dh = wn * 32 + (lane << 1) + ni * 8;
                cbuf[wm * 64 + dh]     = t0;
                cbuf[wm * 64 + dh + 1] = t1;
            }
        }
        __syncthreads();
        if (tid < 64) {
            const int mblk = (m0 & 2047) >> 7;   // 0..15
            g_cb[((size_t)bh * 16 + mblk) * 64 + tid] =
                cbuf[tid] + cbuf[64 + tid] + cbuf[128 + tid] + cbuf[192 + tid];
        }
    }
}

// ---------------------------------------------------------------------------
// Output projection, 2-term (zh*Wh + zh*Wl): 128x64/BK=32, 3-stage.
// A = zh only; W_O hi/lo compensated. Error ~|z_lo|/|z| ~ 3e-4, within budget.
// ---------------------------------------------------------------------------
__global__ __launch_bounds__(256, 2) void gemm_out2(
    const __half* __restrict__ Ah,
    const __half* __restrict__ Bh, const __half* __restrict__ Bl,
    float* __restrict__ C)
{
    extern __shared__ __half sm[];
    const uint32_t sb = smem_u32(sm);
    const int tid = threadIdx.x;
    const int lane = tid & 31, wid = tid >> 5;
    const int wm = wid & 3, wn = wid >> 2;
    const int n0 = blockIdx.x * 64, m0 = blockIdx.y * 128;

    const int lrA = tid >> 1, lpA = tid & 1;
    const int lrB = tid >> 2, lpB = tid & 3;
    const __half* gA  = Ah + (size_t)(m0 + lrA) * 512 + lpA * 16;
    const __half* gBh = Bh + (size_t)(n0 + lrB) * 512 + lpB * 8;
    const __half* gBl = Bl + (size_t)(n0 + lrB) * 512 + lpB * 8;
    const uint32_t dA = sb + (uint32_t)(lrA * SROW2 + lpA * 16) * 2;
    const uint32_t dB = sb + (uint32_t)(lrB * SROW2 + lpB * 8) * 2;

#define LOADCHO2(c, s) { \
        const uint32_t soff = (uint32_t)(s) * (STAGEO * 2); \
        const int ko = (c) * 32; \
        CPASYNC(dA + soff + 0,  gA + ko); \
        CPASYNC(dA + soff + 16, gA + ko + 8); \
        CPASYNC(dB + soff + A_MAT * 2, gBh + ko); \
        CPASYNC(dB + soff + A_MAT * 2 + B_MAT * 2, gBl + ko); \
    }

    float acc[2][4][4];
#pragma unroll
    for (int i = 0; i < 2; i++)
#pragma unroll
        for (int j = 0; j < 4; j++)
#pragma unroll
            for (int k = 0; k < 4; k++) acc[i][j][k] = 0.0f;

    LOADCHO2(0, 0);
    asm volatile("cp.async.commit_group;" ::: "memory");
    LOADCHO2(1, 1);
    asm volatile("cp.async.commit_group;" ::: "memory");

    const uint32_t a_row_off =
        (uint32_t)((wm * 32 + (lane & 15)) * SROW2) * 2 + (uint32_t)((lane >> 4) * 16);
    const int bn = wn * 32 + (lane & 7) + ((lane >> 4) << 3);
    const uint32_t b_row_off =
        (uint32_t)(bn * SROW2) * 2 + (uint32_t)(((lane >> 3) & 1) * 16);

    for (int c = 0; c < 16; c++) {
        if (c < 15) {
            asm volatile("cp.async.wait_group 1;" ::: "memory");
        } else {
            asm volatile("cp.async.wait_group 0;" ::: "memory");
        }
        __syncthreads();
        if (c < 14) {
            LOADCHO2(c + 2, (c + 2) % 3);
            asm volatile("cp.async.commit_group;" ::: "memory");
        }

        const uint32_t base = sb + (uint32_t)(c % 3) * (STAGEO * 2);
#pragma unroll
        for (int kk = 0; kk < 2; kk++) {
            uint32_t A0[4], A1[4], B0h[4], B0l[4], B1h[4], B1l[4];
            const uint32_t aA = base + a_row_off + kk * 32;
            LDSM4(A0, aA);
            LDSM4(A1, aA + 16 * SROW2 * 2);
            const uint32_t bH = base + A_MAT * 2 + b_row_off + kk * 32;
            const uint32_t bL = bH + B_MAT * 2;
            LDSM4(B0h, bH);
            LDSM4(B0l, bL);
            LDSM4(B1h, bH + 16 * SROW2 * 2);
            LDSM4(B1l, bL + 16 * SROW2 * 2);

            MMA(acc[0][0], A0, B0h[0], B0h[1]);
            MMA(acc[1][0], A1, B0h[0], B0h[1]);
            MMA(acc[0][1], A0, B0h[2], B0h[3]);
            MMA(acc[1][1], A1, B0h[2], B0h[3]);
            MMA(acc[0][2], A0, B1h[0], B1h[1]);
            MMA(acc[1][2], A1, B1h[0], B1h[1]);
            MMA(acc[0][3], A0, B1h[2], B1h[3]);
            MMA(acc[1][3], A1, B1h[2], B1h[3]);
            MMA(acc[0][0], A0, B0l[0], B0l[1]);
            MMA(acc[1][0], A1, B0l[0], B0l[1]);
            MMA(acc[0][1], A0, B0l[2], B0l[3]);
            MMA(acc[1][1], A1, B0l[2], B0l[3]);
            MMA(acc[0][2], A0, B1l[0], B1l[1]);
            MMA(acc[1][2], A1, B1l[0], B1l[1]);
            MMA(acc[0][3], A0, B1l[2], B1l[3]);
            MMA(acc[1][3], A1, B1l[2], B1l[3]);
        }
    }

    const int r0 = m0 + wm * 32 + (lane >> 2);
    const int cb = n0 + wn * 32 + (lane & 3) * 2;
#pragma unroll
    for (int mi = 0; mi < 2; mi++) {
        const int r = r0 + mi * 16;
#pragma unroll
        for (int ni = 0; ni < 4; ni++) {
            const int cg = cb + ni * 8;
            *(float2*)&C[(size_t)r * 512 + cg] =
                make_float2(acc[mi][ni][0], acc[mi][ni][1]);
            *(float2*)&C[(size_t)(r + 8) * 512 + cg] =
                make_float2(acc[mi][ni][2], acc[mi][ni][3]);
        }
    }
}

// ---------------------------------------------------------------------------
// Scan: z[q] = a_q*v[q] + c_q*suffix_{p>q} v[p]. Run-in from coarse + fine sums.
// ---------------------------------------------------------------------------
__global__ __launch_bounds__(256) void v_scan()
{
    int bh = blockIdx.y;
    int chunk = blockIdx.x * 4 + (threadIdx.x >> 6);   // 0..127
    int dh = threadIdx.x & 63;
    int b = bh >> 3, h = bh & 7;
    const int q0 = chunk * 16;

    // Run-in: coarse 128-row blocks after this chunk's block + fine chunks
    const int cbk = chunk >> 3;
    float run = 0.0f;
    const float* cbp = g_cb + ((size_t)bh * 16) * 64 + dh;
    for (int j = cbk + 1; j < 16; j++) run += cbp[(size_t)j * 64];
    const float* csp = g_cs + ((size_t)bh * 128) * 64 + dh;
    const int cfEnd = (cbk + 1) << 3;
    for (int cf = chunk + 1; cf < cfEnd; cf++) run += csp[(size_t)cf * 64];

    // Batch all loads up front
    const float* vbase = g_V + (size_t)(b * SEQ + q0) * DMODEL + h * DH + dh;
    float v[16];
#pragma unroll
    for (int i = 0; i < 16; i++) v[i] = vbase[i * DMODEL];

    float wa[16], wc[16];
    const float* sa = g_sa + bh * SEQ + q0;
    const float* sc = g_sc + bh * SEQ + q0;
#pragma unroll
    for (int i = 0; i < 16; i++) { wa[i] = sa[i]; wc[i] = sc[i]; }

    __half* zhb = g_zh + (size_t)(b * SEQ + q0) * DMODEL + h * DH + dh;
#pragma unroll
    for (int i = 15; i >= 0; i--) {
        float z = wa[i] * v[i] + wc[i] * run;
        zhb[i * DMODEL] = __float2half_rn(z);
        run += v[i];
    }
}

// ---------------------------------------------------------------------------
extern "C" void kernel_launch(void* const* d_in, const int* in_sizes, int n_in,
                              void* d_out, int out_size)
{
    const float* x  = (const float*)d_in[0];
    const float* WQ = (const float*)d_in[1];
    const float* WK = (const float*)d_in[2];
    const float* WV = (const float*)d_in[3];
    const float* WO = (const float*)d_in[4];
    float* out = (float*)d_out;

    cudaFuncSetAttribute(qkv_fused, cudaFuncAttributeMaxDynamicSharedMemorySize,
                         SMEM64);
    cudaFuncSetAttribute(gemm_out2, cudaFuncAttributeMaxDynamicSharedMemorySize,
                         SMEMO);

    __half *xh, *xl, *wh, *wl, *oh, *ol, *zh;
    float *gv;
    cudaGetSymbolAddress((void**)&xh, g_xh);
    cudaGetSymbolAddress((void**)&xl, g_xl);
    cudaGetSymbolAddress((void**)&wh, g_wh);
    cudaGetSymbolAddress((void**)&wl, g_wl);
    cudaGetSymbolAddress((void**)&oh, g_oh);
    cudaGetSymbolAddress((void**)&ol, g_ol);
    cudaGetSymbolAddress((void**)&zh, g_zh);
    cudaGetSymbolAddress((void**)&gv, g_V);

    convert_all<<<3072, 256>>>(x, WQ, WK, WV, WO);

    // Fused QK-diag (bx 0..7) + V projection (bx 8..15): 512 CTAs
    qkv_fused<<<dim3(16, 32), 256, SMEM64>>>(xh, xl, wh, wl, gv);

    v_scan<<<dim3(32, 16), 256>>>();

    // Output projection (2-term: zh*(Wh+Wl))
    gemm_out2<<<dim3(8, 32), 256, SMEMO>>>(zh, oh, ol, out);
}